// round 1
// baseline (speedup 1.0000x reference)
#include <cuda_runtime.h>
#include <cuda_bf16.h>

// Problem constants
// x: [32, 512, 512, 3] f32  -> out: [32, 128, 128, 3] f32
// 13-tap separable gaussian (sigma=1.5), zero padding, then out = blur[4i,4j]
#define ROWF4     384          // floats per image row / 4  (512*3/4)
#define SROW      1584         // padded smem row stride in floats (1576 rounded to 16B mult)
#define SMEM_BYTES (16 * SROW * 4)

__device__ __forceinline__ float4 f4zero() { return make_float4(0.f, 0.f, 0.f, 0.f); }

__global__ __launch_bounds__(384, 2)
void aa_fused(const float4* __restrict__ x4, float* __restrict__ out)
{
    extern __shared__ float sm[];          // 16 rows x SROW floats; data at [20, 20+1536)

    const int t  = threadIdx.x;            // 0..383 : one float4 column of the row
    const int n  = blockIdx.y;             // image index
    const int i0 = blockIdx.x << 4;        // first output row of this tile (multiple of 16)

    // 1-D gaussian weights (sigma=1.5, normalized) as literals -> FFMA-imm in SASS
    const float Wt[13] = {
        0.00008922f, 0.00102822f, 0.00759740f, 0.03599436f,
        0.10934121f, 0.21296756f, 0.26596430f, 0.21296756f,
        0.10934121f, 0.03599436f, 0.00759740f, 0.00102822f,
        0.00008922f
    };

    // Zero the horizontal zero-padding regions: per smem row, floats [0,20) and [1556,1576)
    for (int p = t; p < 16 * 40; p += 384) {
        int row = p / 40;
        int o   = p % 40;
        sm[row * SROW + (o < 20 ? o : 1536 + o)] = 0.f;
    }

    // ---------------- Phase 1: vertical blur + row downsample ----------------
    // Rolling register window of 16 float4 rows; slot = input_row & 15.
    // 4*i0 is a multiple of 16, so all slot indices below are compile-time constants.
    const float4* xcol = x4 + (size_t)n * (512 * ROWF4) + t;

    float4 win[16];

    #pragma unroll
    for (int d = -6; d <= 6; ++d) {                 // rows 4*i0-6 .. 4*i0+6
        int r = i0 * 4 + d;
        win[(d + 16) & 15] = (r >= 0) ? __ldg(xcol + r * ROWF4) : f4zero();
    }

    #pragma unroll
    for (int ii = 0; ii < 16; ++ii) {
        float4 acc = f4zero();
        #pragma unroll
        for (int k = 0; k < 13; ++k) {
            const float4 v  = win[(4 * ii + k - 6) & 15];
            const float  wk = Wt[k];
            acc.x = fmaf(wk, v.x, acc.x);
            acc.y = fmaf(wk, v.y, acc.y);
            acc.z = fmaf(wk, v.z, acc.z);
            acc.w = fmaf(wk, v.w, acc.w);
        }
        // store blurred row (output row i0+ii) into padded smem row ii
        *reinterpret_cast<float4*>(&sm[ii * SROW + 20 + 4 * t]) = acc;

        if (ii < 15) {
            // bring in the 4 rows entering the next window: 4*(i0+ii)+7 .. +10
            #pragma unroll
            for (int q = 0; q < 4; ++q) {
                int r = (i0 + ii) * 4 + 7 + q;
                win[(4 * ii + 7 + q) & 15] = (r < 512) ? __ldg(xcol + r * ROWF4) : f4zero();
            }
        }
    }

    __syncthreads();

    // ---------------- Phase 2: horizontal blur + column downsample ----------------
    // thread t -> output (j = t/3, c = t%3); smem addr of col v: 20 + v*3 + c
    const int j    = t / 3;
    const int c    = t - 3 * j;
    const int base = 12 * j + c + 2;       // col (4j - 6) with padding offset folded in

    float* orow = out + (size_t)(n * 128 + i0) * 384 + t;

    #pragma unroll
    for (int rr = 0; rr < 16; ++rr) {
        const float* s = &sm[rr * SROW + base];
        float acc = 0.f;
        #pragma unroll
        for (int k = 0; k < 13; ++k)
            acc = fmaf(Wt[k], s[3 * k], acc);
        orow[rr * 384] = acc;
    }
}

extern "C" void kernel_launch(void* const* d_in, const int* in_sizes, int n_in,
                              void* d_out, int out_size)
{
    (void)in_sizes; (void)n_in; (void)out_size;
    const float4* x4  = (const float4*)d_in[0];
    float*        out = (float*)d_out;

    // dynamic smem > 48KB requires opting in (idempotent; safe during capture)
    cudaFuncSetAttribute(aa_fused, cudaFuncAttributeMaxDynamicSharedMemorySize, SMEM_BYTES);

    dim3 grid(8, 32);          // 8 row-tiles of 16 output rows x 32 images = 256 blocks
    aa_fused<<<grid, 384, SMEM_BYTES>>>(x4, out);
}

// round 2
// speedup vs baseline: 1.1861x; 1.1861x over previous
#include <cuda_runtime.h>
#include <cuda_bf16.h>

// x: [32, 512, 512, 3] f32  -> out: [32, 128, 128, 3] f32
// 13-tap separable gaussian (sigma=1.5), zero padding, out = blur[4i, 4j]
//
// Fused kernel, planar smem staging:
//   Phase 1: vertical 13-tap blur at stride-4 rows, rolling 16-slot float4
//            register window; results scattered into 3 channel planes in smem.
//   Phase 2: horizontal 13-tap blur read as 4 conflict-free LDS.128 per output.

#define ROWF4   384            // float4 per input image row (512*3/4)
#define PROW    528            // floats per padded plane row (8 + 512 + 8)
#define PPLANE  (16 * PROW)    // floats per plane (16 staged rows)     = 8448
#define SMEM_FLOATS (3 * PPLANE)
#define SMEM_BYTES  (SMEM_FLOATS * 4)   // 101376 B -> 2 CTAs/SM

__device__ __forceinline__ float4 f4zero() { return make_float4(0.f, 0.f, 0.f, 0.f); }

__global__ __launch_bounds__(384, 2)
void aa_fused(const float4* __restrict__ x4, float* __restrict__ out)
{
    extern __shared__ float sm[];

    const int t  = threadIdx.x;          // 0..383
    const int n  = blockIdx.y;           // image
    const int i0 = blockIdx.x << 4;      // first output row of tile

    // normalized 1-D gaussian (sigma = 1.5) as literals -> FFMA-imm
    const float Wt[13] = {
        0.00008922f, 0.00102822f, 0.00759740f, 0.03599436f,
        0.10934121f, 0.21296756f, 0.26596430f, 0.21296756f,
        0.10934121f, 0.03599436f, 0.00759740f, 0.00102822f,
        0.00008922f
    };

    // Zero the horizontal padding: per plane-row, floats [0,8) and [520,528)
    for (int p = t; p < 3 * 16 * 16; p += 384) {
        int plane = p >> 8;
        int rem   = p & 255;
        int row   = rem >> 4;
        int o     = rem & 15;
        sm[plane * PPLANE + row * PROW + (o < 8 ? o : 512 + o)] = 0.f;
    }

    // Per-thread planar scatter bases for phase-1 stores.
    // Thread t owns interleaved floats 4t..4t+3 of each blurred row.
    int sbase[4];
    #pragma unroll
    for (int m = 0; m < 4; ++m) {
        int f    = 4 * t + m;
        int col  = f / 3;
        int chan = f - 3 * col;
        sbase[m] = chan * PPLANE + 8 + col;
    }

    // ---------------- Phase 1: vertical blur ----------------
    const float4* xcol = x4 + (size_t)n * (512 * ROWF4) + t;

    float4 win[16];
    #pragma unroll
    for (int d = -6; d <= 6; ++d) {                  // rows 4*i0-6 .. 4*i0+6
        int r = i0 * 4 + d;
        win[(d + 16) & 15] = (r >= 0) ? __ldg(xcol + r * ROWF4) : f4zero();
    }

    #pragma unroll
    for (int ii = 0; ii < 16; ++ii) {
        // Hoisted loads for the NEXT window: rows 4ii+7..9 (their slots are dead).
        if (ii < 15) {
            #pragma unroll
            for (int q = 0; q < 3; ++q) {
                int r = (i0 + ii) * 4 + 7 + q;
                win[(4 * ii + 7 + q) & 15] = (r < 512) ? __ldg(xcol + r * ROWF4) : f4zero();
            }
        }

        // tap k = 0, then recycle its slot for row 4ii+10 (same slot mod 16)
        float4 v0 = win[(4 * ii - 6) & 15];
        float4 acc;
        acc.x = Wt[0] * v0.x;  acc.y = Wt[0] * v0.y;
        acc.z = Wt[0] * v0.z;  acc.w = Wt[0] * v0.w;

        if (ii < 15) {
            int r = (i0 + ii) * 4 + 10;
            win[(4 * ii + 10) & 15] = (r < 512) ? __ldg(xcol + r * ROWF4) : f4zero();
        }

        #pragma unroll
        for (int k = 1; k < 13; ++k) {
            const float4 v  = win[(4 * ii + k - 6) & 15];
            const float  wk = Wt[k];
            acc.x = fmaf(wk, v.x, acc.x);
            acc.y = fmaf(wk, v.y, acc.y);
            acc.z = fmaf(wk, v.z, acc.z);
            acc.w = fmaf(wk, v.w, acc.w);
        }

        // planar scatter: 4 STS.32
        const int ro = ii * PROW;
        sm[sbase[0] + ro] = acc.x;
        sm[sbase[1] + ro] = acc.y;
        sm[sbase[2] + ro] = acc.z;
        sm[sbase[3] + ro] = acc.w;
    }

    __syncthreads();

    // ---------------- Phase 2: horizontal blur ----------------
    // Remap: c = t>>7 (warp-uniform), j = t&127 (consecutive within warp)
    // -> 4 LDS.128 per output, conflict-free (lane stride 64B).
    const int j = t & 127;
    const int c = t >> 7;

    // float4 view of this thread's plane; loads cover plane cols 4j-8 .. 4j+7
    const float4* sp4 = reinterpret_cast<const float4*>(sm) + (c * PPLANE) / 4 + j;

    float* opix = out + ((size_t)(n * 128 + i0) * 128 + j) * 3 + c;

    #pragma unroll
    for (int rr = 0; rr < 16; ++rr) {
        float4 a = sp4[rr * (PROW / 4) + 0];
        float4 b = sp4[rr * (PROW / 4) + 1];
        float4 d = sp4[rr * (PROW / 4) + 2];
        float4 e = sp4[rr * (PROW / 4) + 3];
        // s[0..15] = cols 4j-8 .. 4j+7 ; taps at s[2..14] = cols 4j-6 .. 4j+6
        float acc;
        acc = Wt[0] * a.z;
        acc = fmaf(Wt[1],  a.w, acc);
        acc = fmaf(Wt[2],  b.x, acc);
        acc = fmaf(Wt[3],  b.y, acc);
        acc = fmaf(Wt[4],  b.z, acc);
        acc = fmaf(Wt[5],  b.w, acc);
        acc = fmaf(Wt[6],  d.x, acc);
        acc = fmaf(Wt[7],  d.y, acc);
        acc = fmaf(Wt[8],  d.z, acc);
        acc = fmaf(Wt[9],  d.w, acc);
        acc = fmaf(Wt[10], e.x, acc);
        acc = fmaf(Wt[11], e.y, acc);
        acc = fmaf(Wt[12], e.z, acc);
        opix[rr * 384] = acc;
    }
}

extern "C" void kernel_launch(void* const* d_in, const int* in_sizes, int n_in,
                              void* d_out, int out_size)
{
    (void)in_sizes; (void)n_in; (void)out_size;
    const float4* x4  = (const float4*)d_in[0];
    float*        out = (float*)d_out;

    cudaFuncSetAttribute(aa_fused, cudaFuncAttributeMaxDynamicSharedMemorySize, SMEM_BYTES);

    dim3 grid(8, 32);       // 8 row-tiles x 32 images = 256 CTAs (2/SM, 1 wave)
    aa_fused<<<grid, 384, SMEM_BYTES>>>(x4, out);
}

// round 3
// speedup vs baseline: 1.4426x; 1.2162x over previous
#include <cuda_runtime.h>
#include <cuda_bf16.h>

// x: [32, 512, 512, 3] f32  -> out: [32, 128, 128, 3] f32
// 13-tap separable gaussian (sigma=1.5), zero padding, out = blur[4i, 4j]
//
// Phase 1 (vertical): scatter-accumulate. Input rows streamed sequentially,
//   each row FMAs into the 3-4 output-row accumulators it feeds. All loads
//   independent -> 6-deep prefetch ring fully hides DRAM latency.
// Phase 2 (horizontal): planar smem, 4 conflict-free LDS.128 + 13 FFMA-imm.

#define ROWF4   384            // float4 per input image row (512*3/4)
#define PROW    528            // floats per padded plane row (8 + 512 + 8)
#define NROWS   8              // output rows per tile
#define PPLANE  (NROWS * PROW) // floats per plane               = 4224
#define SMEM_BYTES (3 * PPLANE * 4)   // 50688 B -> 2 CTAs/SM

#define NIN     (4 * NROWS + 9)   // input rows touched per tile = 41
#define PF      6                 // prefetch ring depth

__device__ __forceinline__ float4 f4zero() { return make_float4(0.f, 0.f, 0.f, 0.f); }

__global__ __launch_bounds__(384, 2)
void aa_fused(const float4* __restrict__ x4, float* __restrict__ out)
{
    extern __shared__ float sm[];

    const int t  = threadIdx.x;          // 0..383 : one float4 column of a row
    const int n  = blockIdx.y;           // image
    const int i0 = blockIdx.x * NROWS;   // first output row of tile

    // normalized 1-D gaussian (sigma = 1.5) as literals -> FFMA-imm
    const float Wt[13] = {
        0.00008922f, 0.00102822f, 0.00759740f, 0.03599436f,
        0.10934121f, 0.21296756f, 0.26596430f, 0.21296756f,
        0.10934121f, 0.03599436f, 0.00759740f, 0.00102822f,
        0.00008922f
    };

    // Zero horizontal padding: per plane-row, floats [0,8) and [520,528).
    // 3 planes * 8 rows * 16 pad floats = 384 = blockDim -> one store each.
    {
        int plane = t >> 7;
        int rem   = t & 127;
        int row   = rem >> 4;
        int o     = rem & 15;
        sm[plane * PPLANE + row * PROW + (o < 8 ? o : 512 + o)] = 0.f;
    }

    // Planar scatter bases: thread t owns interleaved floats 4t..4t+3.
    int sbase[4];
    #pragma unroll
    for (int m = 0; m < 4; ++m) {
        int f    = 4 * t + m;
        int col  = f / 3;
        int chan = f - 3 * col;
        sbase[m] = chan * PPLANE + 8 + col;
    }

    // ---------------- Phase 1: vertical blur (scatter-accumulate) ----------------
    const float4* xcol = x4 + (size_t)n * (512 * ROWF4) + t;
    const int R0 = 4 * i0 - 6;                    // first input row (may be <0)

    float4 buf[PF];
    #pragma unroll
    for (int s = 0; s < PF; ++s) {
        int r = R0 + s;
        buf[s] = (r >= 0 && r < 512) ? __ldg(xcol + r * ROWF4) : f4zero();
    }

    float4 acc[NROWS];
    #pragma unroll
    for (int ii = 0; ii < NROWS; ++ii) acc[ii] = f4zero();

    #pragma unroll
    for (int s = 0; s < NIN; ++s) {
        const float4 v = buf[s % PF];

        if (s + PF < NIN) {                       // refill ring (r >= 0 guaranteed)
            int r = R0 + s + PF;
            buf[s % PF] = (r < 512) ? __ldg(xcol + r * ROWF4) : f4zero();
        }

        const int p = s & 3;
        #pragma unroll
        for (int k = p; k <= 12; k += 4) {        // taps congruent to s mod 4
            const int ii = (s - k) >> 2;
            if (ii >= 0 && ii < NROWS) {
                const float wk = Wt[k];
                acc[ii].x = fmaf(wk, v.x, acc[ii].x);
                acc[ii].y = fmaf(wk, v.y, acc[ii].y);
                acc[ii].z = fmaf(wk, v.z, acc[ii].z);
                acc[ii].w = fmaf(wk, v.w, acc[ii].w);
            }
        }
    }

    // Store blurred rows: planar scatter, 4 STS.32 per row
    #pragma unroll
    for (int ii = 0; ii < NROWS; ++ii) {
        const int ro = ii * PROW;
        sm[sbase[0] + ro] = acc[ii].x;
        sm[sbase[1] + ro] = acc[ii].y;
        sm[sbase[2] + ro] = acc[ii].z;
        sm[sbase[3] + ro] = acc[ii].w;
    }

    __syncthreads();

    // ---------------- Phase 2: horizontal blur ----------------
    // c = t>>7 (warp-uniform plane), j = t&127 (consecutive lanes)
    const int j = t & 127;
    const int c = t >> 7;

    const float4* sp4 = reinterpret_cast<const float4*>(sm) + (c * PPLANE) / 4 + j;
    float* opix = out + ((size_t)(n * 128 + i0) * 128 + j) * 3 + c;

    #pragma unroll
    for (int rr = 0; rr < NROWS; ++rr) {
        float4 a = sp4[rr * (PROW / 4) + 0];
        float4 b = sp4[rr * (PROW / 4) + 1];
        float4 d = sp4[rr * (PROW / 4) + 2];
        float4 e = sp4[rr * (PROW / 4) + 3];
        // s[0..15] = cols 4j-8 .. 4j+7 ; taps at s[2..14]
        float acch;
        acch = Wt[0] * a.z;
        acch = fmaf(Wt[1],  a.w, acch);
        acch = fmaf(Wt[2],  b.x, acch);
        acch = fmaf(Wt[3],  b.y, acch);
        acch = fmaf(Wt[4],  b.z, acch);
        acch = fmaf(Wt[5],  b.w, acch);
        acch = fmaf(Wt[6],  d.x, acch);
        acch = fmaf(Wt[7],  d.y, acch);
        acch = fmaf(Wt[8],  d.z, acch);
        acch = fmaf(Wt[9],  d.w, acch);
        acch = fmaf(Wt[10], e.x, acch);
        acch = fmaf(Wt[11], e.y, acch);
        acch = fmaf(Wt[12], e.z, acch);
        opix[rr * 384] = acch;
    }
}

extern "C" void kernel_launch(void* const* d_in, const int* in_sizes, int n_in,
                              void* d_out, int out_size)
{
    (void)in_sizes; (void)n_in; (void)out_size;
    const float4* x4  = (const float4*)d_in[0];
    float*        out = (float*)d_out;

    cudaFuncSetAttribute(aa_fused, cudaFuncAttributeMaxDynamicSharedMemorySize, SMEM_BYTES);

    dim3 grid(16, 32);      // 16 row-tiles of 8 output rows x 32 images = 512 CTAs
    aa_fused<<<grid, 384, SMEM_BYTES>>>(x4, out);
}